// round 13
// baseline (speedup 1.0000x reference)
#include <cuda_runtime.h>
#include <math.h>
#include <stdint.h>

// Problem constants
#define MM    35637
#define KKN   20
#define MKP   712740          // MM*KKN points
#define EPSB  1e-5
#define NBLK  5569            // ceil(MKP/128)

#define PKF   132             // pitch (floats) for A planes and B: 132 % 32 == 4 -> LDSM conflict-free
#define BPITCH 132

typedef unsigned int u32;
typedef unsigned long long ull;

// ---------------- device scratch (static: allocation-guard-safe) ----------------
__device__ float  g_h[91230720];        // 712740 x 128 pre-activations (in-place)
__device__ u32    g_Bt[7 * 128 * BPITCH];  // per-layer weights pre-rounded to tf32 (rna)
__device__ double g_sum[8 * 128];
__device__ double g_ssq[8 * 128];
__device__ float  g_scale[8 * 128];
__device__ float  g_shift[8 * 128];
__device__ double g_inS[7];
__device__ double g_inSS[28];

// ---------------- smem layout (bytes) ----------------
#define OFF_AH   0                       // A hi plane: 128*132*4 = 67584
#define OFF_AL   67584                   // A lo plane: 67584
#define OFF_B    135168                  // B tf32:     67584
#define OFF_RED  202752                  // 256 floats
#define OFF_SC   203776                  // 128 floats
#define OFF_SH   204288                  // 128 floats
#define OFF_X0   204800                  // 128*8 floats (mode0)
#define OFF_W0   208896                  // 128*8 floats (mode0)
#define SMEM_TOTAL 212992

#define ROWB (PKF * 4)                   // 528 bytes per row
#define MTOFF (16 * ROWB)                // 8448: 16-row block stride

// ---------------- helpers ----------------
static __device__ __forceinline__ u32 smem_u32(const void* p) {
    u32 a;
    asm("{ .reg .u64 t; cvta.to.shared.u64 t, %1; cvt.u32.u64 %0, t; }" : "=r"(a) : "l"(p));
    return a;
}
static __device__ __forceinline__ u32 tf32r(float x) {
    u32 r;
    asm("cvt.rna.tf32.f32 %0, %1;" : "=r"(r) : "f"(x));
    return r;
}
static __device__ __forceinline__ void ldsm4(u32* r, u32 addr) {
    asm volatile("ldmatrix.sync.aligned.m8n8.x4.shared.b16 {%0,%1,%2,%3}, [%4];"
                 : "=r"(r[0]), "=r"(r[1]), "=r"(r[2]), "=r"(r[3]) : "r"(addr));
}
static __device__ __forceinline__ void mma8(float* c, const u32* a, const u32* b) {
    asm volatile(
        "mma.sync.aligned.m16n8k8.row.col.f32.tf32.tf32.f32 "
        "{%0,%1,%2,%3}, {%4,%5,%6,%7}, {%8,%9}, {%0,%1,%2,%3};"
        : "+f"(c[0]), "+f"(c[1]), "+f"(c[2]), "+f"(c[3])
        : "r"(a[0]), "r"(a[1]), "r"(a[2]), "r"(a[3]), "r"(b[0]), "r"(b[1]));
}

// ---------------- zero accumulators (must rerun every graph replay) ----------------
__global__ void k_zero() {
    int t = threadIdx.x;
    for (int i = t; i < 1024; i += 256) { g_sum[i] = 0.0; g_ssq[i] = 0.0; }
    if (t < 7)  g_inS[t]  = 0.0;
    if (t < 28) g_inSS[t] = 0.0;
}

// ---------------- per-layer weight pre-round to tf32 (rna), padded pitch ----------------
__global__ void k_prep(const float* __restrict__ convs) {
    int i = blockIdx.x * blockDim.x + threadIdx.x;
    if (i >= 7 * 128 * BPITCH) return;
    int k = i % BPITCH;
    int rest = i / BPITCH;
    int o = rest & 127;
    int w = rest >> 7;
    g_Bt[i] = (k < 128) ? tf32r(convs[w * 16384 + o * 128 + k]) : 0u;
}

// ---------------- input stats: sum(x) [7] and sum(x x^T) [28 triangle] ----------------
__global__ void k_instats(const float* __restrict__ in7) {
    long stride = (long)gridDim.x * blockDim.x;
    float s[7], q[28];
#pragma unroll
    for (int j = 0; j < 7; j++) s[j] = 0.f;
#pragma unroll
    for (int t = 0; t < 28; t++) q[t] = 0.f;

    for (long p = (long)blockIdx.x * blockDim.x + threadIdx.x; p < MKP; p += stride) {
        float x[7];
#pragma unroll
        for (int j = 0; j < 7; j++) x[j] = in7[(long)j * MKP + p];
        int t = 0;
#pragma unroll
        for (int j = 0; j < 7; j++) {
            s[j] += x[j];
#pragma unroll
            for (int jj = j; jj < 7; jj++) { q[t] += x[j] * x[jj]; t++; }
        }
    }
#pragma unroll
    for (int j = 0; j < 7; j++)
        for (int off = 16; off; off >>= 1) s[j] += __shfl_down_sync(0xffffffffu, s[j], off);
#pragma unroll
    for (int t = 0; t < 28; t++)
        for (int off = 16; off; off >>= 1) q[t] += __shfl_down_sync(0xffffffffu, q[t], off);

    if ((threadIdx.x & 31) == 0) {
#pragma unroll
        for (int j = 0; j < 7; j++) atomicAdd(&g_inS[j], (double)s[j]);
#pragma unroll
        for (int t = 0; t < 28; t++) atomicAdd(&g_inSS[t], (double)q[t]);
    }
}

// ---------------- BN0 params analytically from input moments ----------------
__global__ void k_fin0(const float* __restrict__ W0,
                       const float* __restrict__ gammas,
                       const float* __restrict__ betas) {
    int c = threadIdx.x;  // 128
    double S[7], SS[7][7];
#pragma unroll
    for (int j = 0; j < 7; j++) S[j] = g_inS[j];
    int t = 0;
    for (int j = 0; j < 7; j++)
        for (int jj = j; jj < 7; jj++) { SS[j][jj] = g_inSS[t]; SS[jj][j] = g_inSS[t]; t++; }
    double w[7];
#pragma unroll
    for (int j = 0; j < 7; j++) w[j] = (double)W0[c * 7 + j];
    double mu = 0.0;
#pragma unroll
    for (int j = 0; j < 7; j++) mu += w[j] * S[j];
    mu /= (double)MKP;
    double e2 = 0.0;
    for (int j = 0; j < 7; j++)
        for (int jj = 0; jj < 7; jj++) e2 += w[j] * w[jj] * SS[j][jj];
    e2 /= (double)MKP;
    double var = e2 - mu * mu;
    double scl = (double)gammas[c] / sqrt(var + EPSB);
    g_scale[c] = (float)scl;
    g_shift[c] = (float)((double)betas[c] - mu * scl);
}

// ---------------- BN params for layer L ----------------
__global__ void k_fin(int L, const float* __restrict__ gammas, const float* __restrict__ betas) {
    int c = threadIdx.x;  // 128
    double mu  = g_sum[L * 128 + c] / (double)MKP;
    double var = g_ssq[L * 128 + c] / (double)MKP - mu * mu;
    double scl = (double)gammas[L * 128 + c] / sqrt(var + EPSB);
    g_scale[L * 128 + c] = (float)scl;
    g_shift[L * 128 + c] = (float)((double)betas[L * 128 + c] - mu * scl);
}

// ---------------- fused pass: act=sin(BN(h)), h' = act @ W^T (split-A tf32 mma), stats ----------------
// 512 threads, 16 warps (4x4 warp grid, 32x32 per warp). Chunk-pipelined: the 128
// channels are processed in 4 chunks of 32; mma(ch) overlaps build(ch+1) so the
// tensor/LDS pipes run concurrently with the MUFU sine work.
__global__ void __launch_bounds__(512, 1)
k_gemm(const float* __restrict__ src, const float* __restrict__ W0c,
       int wIdx, int actL, int statL, int mode) {
    extern __shared__ char sm[];
    float* AsH = (float*)(sm + OFF_AH);
    float* AsL = (float*)(sm + OFF_AL);
    float* red = (float*)(sm + OFF_RED);
    float* scs = (float*)(sm + OFF_SC);
    float* shs = (float*)(sm + OFF_SH);
    float* xs0 = (float*)(sm + OFF_X0);
    float* w0s = (float*)(sm + OFF_W0);

    const u32 sb   = smem_u32(sm);
    const int tid  = threadIdx.x;
    const int wid  = tid >> 5;
    const int lane = tid & 31;
    const int lg   = lane >> 2;
    const int lq   = lane & 3;
    const int wm   = wid & 3;     // 32-row band
    const int wn   = wid >> 2;    // 32-col band
    const long p0  = (long)blockIdx.x * 128;

    // --- async B tile fetch (pre-rounded tf32, linear copy incl. pad) ---
    {
        const u32* gsrc = g_Bt + (long)wIdx * (128 * BPITCH);
        u32 db = sb + OFF_B;
#pragma unroll 1
        for (int i = tid; i < (128 * BPITCH) / 4; i += 512) {
            asm volatile("cp.async.cg.shared.global [%0], [%1], 16;"
                         :: "r"(db + i * 16), "l"(gsrc + i * 4) : "memory");
        }
        asm volatile("cp.async.commit_group;" ::: "memory");
    }

    if (tid < 128) {
        scs[tid] = g_scale[actL * 128 + tid];
        shs[tid] = g_shift[actL * 128 + tid];
    }
    if (tid < 256) red[tid] = 0.f;
    if (mode == 0) {
        for (int t = tid; t < 1024; t += 512) {
            int p = t >> 3, j = t & 7;
            xs0[t] = (j < 7 && p0 + p < MKP) ? src[(long)j * MKP + p0 + p] : 0.f;
        }
        for (int t = tid; t < 1024; t += 512) {
            int c = t >> 3, j = t & 7;
            w0s[t] = (j < 7) ? W0c[c * 7 + j] : 0.f;
        }
    }
    __syncthreads();

    // ---- per-chunk activation build (32 channels = 8 quads x 128 rows = 1024 items, 2 iters) ----
    // mode 1: act from g_h; mode 0: act from conv0(x)
#define BUILD_CHUNK(chBase_)                                                          \
    do {                                                                              \
        const int chBase = (chBase_);                                                 \
        int itA = tid, itB = 512 + tid;                                               \
        int pA = itA >> 3, cA = chBase + ((itA & 7) << 2);                            \
        int pB = itB >> 3, cB = chBase + ((itB & 7) << 2);                            \
        long pgA = p0 + pA, pgB = p0 + pB;                                            \
        bool inA = (pgA < MKP), inB = (pgB < MKP);                                    \
        if (mode == 0) {                                                              \
            float hiA[4], loA[4], hiB[4], loB[4];                                     \
            _Pragma("unroll")                                                         \
            for (int e = 0; e < 4; e++) {                                             \
                float v = 0.f;                                                        \
                _Pragma("unroll")                                                     \
                for (int jj = 0; jj < 7; jj++)                                        \
                    v = fmaf(w0s[(cA + e) * 8 + jj], xs0[pA * 8 + jj], v);            \
                float a = inA ? __sinf(fmaf(scs[cA + e], v, shs[cA + e])) : 0.f;      \
                u32 hb = __float_as_uint(a) & 0xFFFFE000u;                            \
                hiA[e] = __uint_as_float(hb); loA[e] = a - hiA[e];                    \
            }                                                                         \
            _Pragma("unroll")                                                         \
            for (int e = 0; e < 4; e++) {                                             \
                float v = 0.f;                                                        \
                _Pragma("unroll")                                                     \
                for (int jj = 0; jj < 7; jj++)                                        \
                    v = fmaf(w0s[(cB + e) * 8 + jj], xs0[pB * 8 + jj], v);            \
                float a = inB ? __sinf(fmaf(scs[cB + e], v, shs[cB + e])) : 0.f;      \
                u32 hb = __float_as_uint(a) & 0xFFFFE000u;                            \
                hiB[e] = __uint_as_float(hb); loB[e] = a - hiB[e];                    \
            }                                                                         \
            *(float4*)&AsH[pA * PKF + cA] = make_float4(hiA[0], hiA[1], hiA[2], hiA[3]); \
            *(float4*)&AsL[pA * PKF + cA] = make_float4(loA[0], loA[1], loA[2], loA[3]); \
            *(float4*)&AsH[pB * PKF + cB] = make_float4(hiB[0], hiB[1], hiB[2], hiB[3]); \
            *(float4*)&AsL[pB * PKF + cB] = make_float4(loB[0], loB[1], loB[2], loB[3]); \
        } else {                                                                      \
            float4 hvA = inA ? *(const float4*)&g_h[pgA * 128 + cA]                   \
                             : make_float4(0.f, 0.f, 0.f, 0.f);                       \
            float4 hvB = inB ? *(const float4*)&g_h[pgB * 128 + cB]                   \
                             : make_float4(0.f, 0.f, 0.f, 0.f);                       \
            float vvA[4] = {hvA.x, hvA.y, hvA.z, hvA.w};                              \
            float vvB[4] = {hvB.x, hvB.y, hvB.z, hvB.w};                              \
            float hiA[4], loA[4], hiB[4], loB[4];                                     \
            _Pragma("unroll")                                                         \
            for (int e = 0; e < 4; e++) {                                             \
                float a = inA ? __sinf(fmaf(scs[cA + e], vvA[e], shs[cA + e])) : 0.f; \
                u32 hb = __float_as_uint(a) & 0xFFFFE000u;                            \
                hiA[e] = __uint_as_float(hb); loA[e] = a - hiA[e];                    \
            }                                                                         \
            _Pragma("unroll")                                                         \
            for (int e = 0; e < 4; e++) {                                             \
                float a = inB ? __sinf(fmaf(scs[cB + e], vvB[e], shs[cB + e])) : 0.f; \
                u32 hb = __float_as_uint(a) & 0xFFFFE000u;                            \
                hiB[e] = __uint_as_float(hb); loB[e] = a - hiB[e];                    \
            }                                                                         \
            *(float4*)&AsH[pA * PKF + cA] = make_float4(hiA[0], hiA[1], hiA[2], hiA[3]); \
            *(float4*)&AsL[pA * PKF + cA] = make_float4(loA[0], loA[1], loA[2], loA[3]); \
            *(float4*)&AsH[pB * PKF + cB] = make_float4(hiB[0], hiB[1], hiB[2], hiB[3]); \
            *(float4*)&AsL[pB * PKF + cB] = make_float4(loB[0], loB[1], loB[2], loB[3]); \
        }                                                                             \
    } while (0)

    // --- accumulators + LDSM lane addresses ---
    float acc[2][4][4];
#pragma unroll
    for (int mt = 0; mt < 2; mt++)
#pragma unroll
        for (int nt = 0; nt < 4; nt++)
#pragma unroll
            for (int e = 0; e < 4; e++) acc[mt][nt][e] = 0.f;

    const u32 aHiB = sb + OFF_AH + (u32)((wm * 32 + (lane & 15)) * ROWB) + ((lane >> 4) & 1) * 16;
    const u32 aLoB = aHiB + (OFF_AL - OFF_AH);
    const u32 bB = sb + OFF_B
                 + (u32)((wn * 32 + (lane & 7) + ((lane >> 4) & 1) * 8) * ROWB)
                 + ((lane >> 3) & 1) * 16;

    // --- pipeline: build(0); bar; { mma(ch) || build(ch+1); bar; } x4 ---
    BUILD_CHUNK(0);
    asm volatile("cp.async.wait_group 0;" ::: "memory");
    __syncthreads();

#pragma unroll
    for (int ch = 0; ch < 4; ch++) {
#pragma unroll
        for (int kk = 0; kk < 4; kk++) {
            const u32 kb = (ch * 4 + kk) * 32;
            u32 ah0[4], ah1[4], al0[4], al1[4], bA[4], bC[4];
            ldsm4(ah0, aHiB + kb);
            ldsm4(ah1, aHiB + MTOFF + kb);
            ldsm4(al0, aLoB + kb);
            ldsm4(al1, aLoB + MTOFF + kb);
            ldsm4(bA, bB + kb);
            ldsm4(bC, bB + MTOFF + kb);

            mma8(acc[0][0], ah0, bA);     mma8(acc[0][0], al0, bA);
            mma8(acc[0][1], ah0, bA + 2); mma8(acc[0][1], al0, bA + 2);
            mma8(acc[0][2], ah0, bC);     mma8(acc[0][2], al0, bC);
            mma8(acc[0][3], ah0, bC + 2); mma8(acc[0][3], al0, bC + 2);
            mma8(acc[1][0], ah1, bA);     mma8(acc[1][0], al1, bA);
            mma8(acc[1][1], ah1, bA + 2); mma8(acc[1][1], al1, bA + 2);
            mma8(acc[1][2], ah1, bC);     mma8(acc[1][2], al1, bC);
            mma8(acc[1][3], ah1, bC + 2); mma8(acc[1][3], al1, bC + 2);
        }
        if (ch < 3) BUILD_CHUNK((ch + 1) * 32);
        __syncthreads();
    }

    // --- epilogue: store h_l, per-channel stats (shfl-reduced over lg) ---
#pragma unroll
    for (int mt = 0; mt < 2; mt++) {
        long rA = p0 + wm * 32 + mt * 16 + lg;
        long rB = rA + 8;
        bool vA = (rA < MKP), vB = (rB < MKP);
#pragma unroll
        for (int nt = 0; nt < 4; nt++) {
            int c0 = wn * 32 + nt * 8 + lq * 2;
            if (vA) *(float2*)&g_h[rA * 128 + c0] = make_float2(acc[mt][nt][0], acc[mt][nt][1]);
            if (vB) *(float2*)&g_h[rB * 128 + c0] = make_float2(acc[mt][nt][2], acc[mt][nt][3]);
        }
    }
#pragma unroll
    for (int nt = 0; nt < 4; nt++) {
        int c0 = wn * 32 + nt * 8 + lq * 2;
#pragma unroll
        for (int par = 0; par < 2; par++) {
            float v0 = acc[0][nt][par],     v1 = acc[0][nt][2 + par];
            float v2 = acc[1][nt][par],     v3 = acc[1][nt][2 + par];
            float s = (v0 + v1) + (v2 + v3);
            float q = fmaf(v0, v0, fmaf(v1, v1, fmaf(v2, v2, v3 * v3)));
            s += __shfl_xor_sync(0xffffffffu, s, 4);
            q += __shfl_xor_sync(0xffffffffu, q, 4);
            s += __shfl_xor_sync(0xffffffffu, s, 8);
            q += __shfl_xor_sync(0xffffffffu, q, 8);
            s += __shfl_xor_sync(0xffffffffu, s, 16);
            q += __shfl_xor_sync(0xffffffffu, q, 16);
            if (lg == 0) {
                atomicAdd(&red[c0 + par], s);
                atomicAdd(&red[128 + c0 + par], q);
            }
        }
    }
    __syncthreads();
    if (tid < 128) {
        atomicAdd(&g_sum[statL * 128 + tid], (double)red[tid]);
        atomicAdd(&g_ssq[statL * 128 + tid], (double)red[128 + tid]);
    }
}

// ---------------- final: act7 -> logits -> softmax(K) -> gather+weighted sum ----------------
__global__ void k_final(const float* __restrict__ xfeat, const int* __restrict__ idx,
                        const float* __restrict__ fw, const float* __restrict__ fb,
                        float* __restrict__ out) {
    __shared__ float prod[20][128];
    __shared__ float wsm[20];
    __shared__ float logit[20];
    __shared__ int   idxs[20];

    const int m = blockIdx.x;
    const int tid = threadIdx.x;  // 128
    const float sc = g_scale[7 * 128 + tid];
    const float sh = g_shift[7 * 128 + tid];
    const float f  = fw[tid];
    const float* hrow = g_h + (long)m * 20 * 128;

    if (tid < 20) idxs[tid] = idx[m * 20 + tid];
#pragma unroll
    for (int k = 0; k < 20; k++) {
        float v = hrow[k * 128 + tid];
        prod[k][tid] = __sinf(fmaf(sc, v, sh)) * f;
    }
    __syncthreads();

    const int w = tid >> 5, lane = tid & 31;
    for (int k = w; k < 20; k += 4) {
        float sum = prod[k][lane] + prod[k][lane + 32] + prod[k][lane + 64] + prod[k][lane + 96];
        for (int off = 16; off; off >>= 1) sum += __shfl_down_sync(0xffffffffu, sum, off);
        if (lane == 0) logit[k] = sum + fb[0];
    }
    __syncthreads();

    if (tid < 32) {
        float l = (tid < 20) ? logit[tid] : -INFINITY;
        float mx = l;
        for (int off = 16; off; off >>= 1) mx = fmaxf(mx, __shfl_xor_sync(0xffffffffu, mx, off));
        float e = (tid < 20) ? expf(l - mx) : 0.f;
        float ss = e;
        for (int off = 16; off; off >>= 1) ss += __shfl_xor_sync(0xffffffffu, ss, off);
        if (tid < 20) wsm[tid] = e / ss;
    }
    __syncthreads();

    float acc = 0.f;
#pragma unroll
    for (int k = 0; k < 20; k++)
        acc += wsm[k] * xfeat[(long)idxs[k] * 128 + tid];
    out[(long)m * 128 + tid] = acc;
}

// ---------------- launch ----------------
extern "C" void kernel_launch(void* const* d_in, const int* in_sizes, int n_in,
                              void* d_out, int out_size) {
    const float* xfeat  = (const float*)d_in[0];  // (1, N, 128)
    const float* w_up   = (const float*)d_in[1];  // (1, 7, M, K)
    const int*   idx    = (const int*)d_in[2];    // (1, M, K)
    const float* conv0  = (const float*)d_in[3];  // (128, 7)
    const float* convs  = (const float*)d_in[4];  // (7, 128, 128)
    const float* gammas = (const float*)d_in[5];  // (8, 128)
    const float* betas  = (const float*)d_in[6];  // (8, 128)
    const float* fw     = (const float*)d_in[7];  // (1, 128)
    const float* fb     = (const float*)d_in[8];  // (1,)
    float* out = (float*)d_out;

    cudaFuncSetAttribute(k_gemm, cudaFuncAttributeMaxDynamicSharedMemorySize, SMEM_TOTAL);

    k_zero<<<1, 256>>>();
    k_prep<<<(7 * 128 * BPITCH + 255) / 256, 256>>>(convs);
    k_instats<<<256, 256>>>(w_up);
    k_fin0<<<1, 128>>>(conv0, gammas, betas);

    // Layer 1: act0 from raw input (conv0 scalar + BN0 + sin), GEMM W1, stats
    k_gemm<<<NBLK, 512, SMEM_TOTAL>>>(w_up, conv0, 0, 0, 1, 0);
    k_fin<<<1, 128>>>(1, gammas, betas);

    // Layers 2..7
    for (int i = 2; i <= 7; i++) {
        k_gemm<<<NBLK, 512, SMEM_TOTAL>>>(nullptr, nullptr, i - 1, i - 1, i, 1);
        k_fin<<<1, 128>>>(i, gammas, betas);
    }

    k_final<<<MM, 128>>>(xfeat, idx, fw, fb, out);
}

// round 14
// speedup vs baseline: 1.8046x; 1.8046x over previous
#include <cuda_runtime.h>
#include <math.h>
#include <stdint.h>

// Problem constants
#define MM    35637
#define KKN   20
#define MKP   712740          // MM*KKN points
#define EPSB  1e-5
#define MTILE 64
#define NBLK2 11137           // ceil(MKP/64)

#define PKA   68              // pitch (words) for A half-planes and B halves: 68 % 32 == 4 -> LDSM conflict-free
#define ROWB2 272             // PKA*4 bytes
#define MT16  (16 * ROWB2)    // 16-row block stride = 4352

typedef unsigned int u32;
typedef unsigned long long ull;

// ---------------- device scratch (static: allocation-guard-safe) ----------------
__device__ float  g_h[91230720];          // 712740 x 128 pre-activations (in-place)
__device__ u32    g_Bt[7 * 2 * 128 * PKA];   // per-layer weights tf32(rna), [layer][khalf][n][68]
__device__ double g_sum[8 * 128];
__device__ double g_ssq[8 * 128];
__device__ float  g_scale[8 * 128];
__device__ float  g_shift[8 * 128];
__device__ double g_inS[7];
__device__ double g_inSS[28];

// ---------------- smem layout (bytes) ----------------
#define OFF_AH   0            // A hi half-plane: 64*272 = 17408
#define OFF_AL   17408        // A lo half-plane: 17408
#define OFF_B0   34816        // B half 0: 128*272 = 34816
#define OFF_B1   69632        // B half 1: 34816
#define OFF_RED  104448       // 256 floats
#define OFF_SC   105472       // 128 floats
#define OFF_SH   105984       // 128 floats
#define OFF_X0   106496       // 64*8 floats (mode0)
#define OFF_W0   108544       // 128*8 floats (mode0)
#define SMEM_TOTAL 112640     // 110 KB -> 2 CTAs/SM

// ---------------- helpers ----------------
static __device__ __forceinline__ u32 smem_u32(const void* p) {
    u32 a;
    asm("{ .reg .u64 t; cvta.to.shared.u64 t, %1; cvt.u32.u64 %0, t; }" : "=r"(a) : "l"(p));
    return a;
}
static __device__ __forceinline__ u32 tf32r(float x) {
    u32 r;
    asm("cvt.rna.tf32.f32 %0, %1;" : "=r"(r) : "f"(x));
    return r;
}
static __device__ __forceinline__ void ldsm4(u32* r, u32 addr) {
    asm volatile("ldmatrix.sync.aligned.m8n8.x4.shared.b16 {%0,%1,%2,%3}, [%4];"
                 : "=r"(r[0]), "=r"(r[1]), "=r"(r[2]), "=r"(r[3]) : "r"(addr));
}
static __device__ __forceinline__ void mma8(float* c, const u32* a, const u32* b) {
    asm volatile(
        "mma.sync.aligned.m16n8k8.row.col.f32.tf32.tf32.f32 "
        "{%0,%1,%2,%3}, {%4,%5,%6,%7}, {%8,%9}, {%0,%1,%2,%3};"
        : "+f"(c[0]), "+f"(c[1]), "+f"(c[2]), "+f"(c[3])
        : "r"(a[0]), "r"(a[1]), "r"(a[2]), "r"(a[3]), "r"(b[0]), "r"(b[1]));
}

// ---------------- zero accumulators (must rerun every graph replay) ----------------
__global__ void k_zero() {
    int t = threadIdx.x;
    for (int i = t; i < 1024; i += 256) { g_sum[i] = 0.0; g_ssq[i] = 0.0; }
    if (t < 7)  g_inS[t]  = 0.0;
    if (t < 28) g_inSS[t] = 0.0;
}

// ---------------- per-layer weight pre-round to tf32 (rna), K-half split, pitch 68 ----------------
__global__ void k_prep(const float* __restrict__ convs) {
    int i = blockIdx.x * blockDim.x + threadIdx.x;
    if (i >= 7 * 2 * 128 * PKA) return;
    int k = i % PKA;
    int n = (i / PKA) & 127;
    int half = (i / (PKA * 128)) & 1;
    int layer = i / (PKA * 256);
    g_Bt[i] = (k < 64) ? tf32r(convs[layer * 16384 + n * 128 + half * 64 + k]) : 0u;
}

// ---------------- input stats: sum(x) [7] and sum(x x^T) [28 triangle] ----------------
__global__ void k_instats(const float* __restrict__ in7) {
    long stride = (long)gridDim.x * blockDim.x;
    float s[7], q[28];
#pragma unroll
    for (int j = 0; j < 7; j++) s[j] = 0.f;
#pragma unroll
    for (int t = 0; t < 28; t++) q[t] = 0.f;

    for (long p = (long)blockIdx.x * blockDim.x + threadIdx.x; p < MKP; p += stride) {
        float x[7];
#pragma unroll
        for (int j = 0; j < 7; j++) x[j] = in7[(long)j * MKP + p];
        int t = 0;
#pragma unroll
        for (int j = 0; j < 7; j++) {
            s[j] += x[j];
#pragma unroll
            for (int jj = j; jj < 7; jj++) { q[t] += x[j] * x[jj]; t++; }
        }
    }
#pragma unroll
    for (int j = 0; j < 7; j++)
        for (int off = 16; off; off >>= 1) s[j] += __shfl_down_sync(0xffffffffu, s[j], off);
#pragma unroll
    for (int t = 0; t < 28; t++)
        for (int off = 16; off; off >>= 1) q[t] += __shfl_down_sync(0xffffffffu, q[t], off);

    if ((threadIdx.x & 31) == 0) {
#pragma unroll
        for (int j = 0; j < 7; j++) atomicAdd(&g_inS[j], (double)s[j]);
#pragma unroll
        for (int t = 0; t < 28; t++) atomicAdd(&g_inSS[t], (double)q[t]);
    }
}

// ---------------- BN0 params analytically from input moments ----------------
__global__ void k_fin0(const float* __restrict__ W0,
                       const float* __restrict__ gammas,
                       const float* __restrict__ betas) {
    int c = threadIdx.x;  // 128
    double S[7], SS[7][7];
#pragma unroll
    for (int j = 0; j < 7; j++) S[j] = g_inS[j];
    int t = 0;
    for (int j = 0; j < 7; j++)
        for (int jj = j; jj < 7; jj++) { SS[j][jj] = g_inSS[t]; SS[jj][j] = g_inSS[t]; t++; }
    double w[7];
#pragma unroll
    for (int j = 0; j < 7; j++) w[j] = (double)W0[c * 7 + j];
    double mu = 0.0;
#pragma unroll
    for (int j = 0; j < 7; j++) mu += w[j] * S[j];
    mu /= (double)MKP;
    double e2 = 0.0;
    for (int j = 0; j < 7; j++)
        for (int jj = 0; jj < 7; jj++) e2 += w[j] * w[jj] * SS[j][jj];
    e2 /= (double)MKP;
    double var = e2 - mu * mu;
    double scl = (double)gammas[c] / sqrt(var + EPSB);
    g_scale[c] = (float)scl;
    g_shift[c] = (float)((double)betas[c] - mu * scl);
}

// ---------------- BN params for layer L ----------------
__global__ void k_fin(int L, const float* __restrict__ gammas, const float* __restrict__ betas) {
    int c = threadIdx.x;  // 128
    double mu  = g_sum[L * 128 + c] / (double)MKP;
    double var = g_ssq[L * 128 + c] / (double)MKP - mu * mu;
    double scl = (double)gammas[L * 128 + c] / sqrt(var + EPSB);
    g_scale[L * 128 + c] = (float)scl;
    g_shift[L * 128 + c] = (float)((double)betas[L * 128 + c] - mu * scl);
}

// ---------------- fused pass: act=sin(BN(h)), h' = act @ W^T (split-A tf32 mma), stats ----------------
// 256 threads, 8 warps (2x4 warp grid, 32x32 per warp), M-tile 64, K in 2 halves
// with A half-planes reused. 110KB smem -> 2 CTAs/SM so one CTA's build (MUFU/LDG)
// overlaps the other's MMA (tensor/LDS).
__global__ void __launch_bounds__(256, 2)
k_gemm(const float* __restrict__ src, const float* __restrict__ W0c,
       int wIdx, int actL, int statL, int mode) {
    extern __shared__ char sm[];
    float* AsH = (float*)(sm + OFF_AH);
    float* AsL = (float*)(sm + OFF_AL);
    float* red = (float*)(sm + OFF_RED);
    float* scs = (float*)(sm + OFF_SC);
    float* shs = (float*)(sm + OFF_SH);
    float* xs0 = (float*)(sm + OFF_X0);
    float* w0s = (float*)(sm + OFF_W0);

    const u32 sb   = smem_u32(sm);
    const int tid  = threadIdx.x;
    const int wid  = tid >> 5;
    const int lane = tid & 31;
    const int lg   = lane >> 2;
    const int lq   = lane & 3;
    const int wm   = wid & 1;     // 32-row band (of 64)
    const int wn   = wid >> 1;    // 32-col band (of 128)
    const long p0  = (long)blockIdx.x * MTILE;

    // --- async fetch of both B halves (pre-rounded tf32, pitched) ---
    {
        const u32* gsrc = g_Bt + (long)wIdx * (2 * 128 * PKA);
        u32 db = sb + OFF_B0;
#pragma unroll 1
        for (int i = tid; i < (2 * 128 * PKA) / 4; i += 256) {
            asm volatile("cp.async.cg.shared.global [%0], [%1], 16;"
                         :: "r"(db + i * 16), "l"(gsrc + i * 4) : "memory");
        }
        asm volatile("cp.async.commit_group;" ::: "memory");
    }

    if (tid < 128) {
        scs[tid] = g_scale[actL * 128 + tid];
        shs[tid] = g_shift[actL * 128 + tid];
    }
    red[tid] = 0.f;  // 256 covers sum[128]+ssq[128]
    if (mode == 0) {
        for (int t = tid; t < 512; t += 256) {
            int p = t >> 3, j = t & 7;
            xs0[t] = (j < 7 && p0 + p < MKP) ? src[(long)j * MKP + p0 + p] : 0.f;
        }
        for (int t = tid; t < 1024; t += 256) {
            int c = t >> 3, j = t & 7;
            w0s[t] = (j < 7) ? W0c[c * 7 + j] : 0.f;
        }
    }
    __syncthreads();

    // ---- build A half-plane (64 ch): 64 rows x 16 quads = 1024 items, 4 iters ----
#define BUILD_HALF(chBase_)                                                           \
    do {                                                                              \
        const int chBase = (chBase_);                                                 \
        if (mode == 0) {                                                              \
            _Pragma("unroll")                                                         \
            for (int itr = 0; itr < 4; itr++) {                                       \
                int it = itr * 256 + tid;                                             \
                int p = it >> 4, cl = (it & 15) << 2;                                 \
                int cg = chBase + cl;                                                 \
                bool inb = (p0 + p < MKP);                                            \
                float hi[4], lo[4];                                                   \
                _Pragma("unroll")                                                     \
                for (int e = 0; e < 4; e++) {                                         \
                    float v = 0.f;                                                    \
                    _Pragma("unroll")                                                 \
                    for (int jj = 0; jj < 7; jj++)                                    \
                        v = fmaf(w0s[(cg + e) * 8 + jj], xs0[p * 8 + jj], v);         \
                    float a = inb ? __sinf(fmaf(scs[cg + e], v, shs[cg + e])) : 0.f;  \
                    u32 hb = __float_as_uint(a) & 0xFFFFE000u;                        \
                    hi[e] = __uint_as_float(hb); lo[e] = a - hi[e];                   \
                }                                                                     \
                *(float4*)&AsH[p * PKA + cl] = make_float4(hi[0], hi[1], hi[2], hi[3]); \
                *(float4*)&AsL[p * PKA + cl] = make_float4(lo[0], lo[1], lo[2], lo[3]); \
            }                                                                         \
        } else {                                                                      \
            float4 hv[4];                                                             \
            _Pragma("unroll")                                                         \
            for (int itr = 0; itr < 4; itr++) {                                       \
                int it = itr * 256 + tid;                                             \
                int p = it >> 4, cl = (it & 15) << 2;                                 \
                long pg = p0 + p;                                                     \
                hv[itr] = (pg < MKP) ? *(const float4*)&g_h[pg * 128 + chBase + cl]   \
                                     : make_float4(0.f, 0.f, 0.f, 0.f);               \
            }                                                                         \
            _Pragma("unroll")                                                         \
            for (int itr = 0; itr < 4; itr++) {                                       \
                int it = itr * 256 + tid;                                             \
                int p = it >> 4, cl = (it & 15) << 2;                                 \
                int cg = chBase + cl;                                                 \
                bool inb = (p0 + p < MKP);                                            \
                float vv[4] = {hv[itr].x, hv[itr].y, hv[itr].z, hv[itr].w};           \
                float hi[4], lo[4];                                                   \
                _Pragma("unroll")                                                     \
                for (int e = 0; e < 4; e++) {                                         \
                    float a = inb ? __sinf(fmaf(scs[cg + e], vv[e], shs[cg + e])) : 0.f; \
                    u32 hb = __float_as_uint(a) & 0xFFFFE000u;                        \
                    hi[e] = __uint_as_float(hb); lo[e] = a - hi[e];                   \
                }                                                                     \
                *(float4*)&AsH[p * PKA + cl] = make_float4(hi[0], hi[1], hi[2], hi[3]); \
                *(float4*)&AsL[p * PKA + cl] = make_float4(lo[0], lo[1], lo[2], lo[3]); \
            }                                                                         \
        }                                                                             \
    } while (0)

    // --- accumulators + LDSM lane addresses ---
    float acc[2][4][4];
#pragma unroll
    for (int mt = 0; mt < 2; mt++)
#pragma unroll
        for (int nt = 0; nt < 4; nt++)
#pragma unroll
            for (int e = 0; e < 4; e++) acc[mt][nt][e] = 0.f;

    const u32 aHiB = sb + OFF_AH + (u32)((wm * 32 + (lane & 15)) * ROWB2) + ((lane >> 4) & 1) * 16;
    const u32 aLoB = aHiB + (OFF_AL - OFF_AH);
    const u32 bB0 = sb + OFF_B0
                  + (u32)((wn * 32 + (lane & 7) + ((lane >> 4) & 1) * 8) * ROWB2)
                  + ((lane >> 3) & 1) * 16;

#define MMA_HALF(bBase_)                                                      \
    do {                                                                      \
        _Pragma("unroll")                                                     \
        for (int kk = 0; kk < 8; kk++) {                                      \
            const u32 kb = kk * 32;                                           \
            u32 ah0[4], ah1[4], al0[4], al1[4], bA[4], bC[4];                 \
            ldsm4(ah0, aHiB + kb);                                            \
            ldsm4(ah1, aHiB + MT16 + kb);                                     \
            ldsm4(al0, aLoB + kb);                                            \
            ldsm4(al1, aLoB + MT16 + kb);                                     \
            ldsm4(bA, (bBase_) + kb);                                         \
            ldsm4(bC, (bBase_) + MT16 + kb);                                  \
            mma8(acc[0][0], ah0, bA);     mma8(acc[0][0], al0, bA);           \
            mma8(acc[0][1], ah0, bA + 2); mma8(acc[0][1], al0, bA + 2);       \
            mma8(acc[0][2], ah0, bC);     mma8(acc[0][2], al0, bC);           \
            mma8(acc[0][3], ah0, bC + 2); mma8(acc[0][3], al0, bC + 2);       \
            mma8(acc[1][0], ah1, bA);     mma8(acc[1][0], al1, bA);           \
            mma8(acc[1][1], ah1, bA + 2); mma8(acc[1][1], al1, bA + 2);       \
            mma8(acc[1][2], ah1, bC);     mma8(acc[1][2], al1, bC);           \
            mma8(acc[1][3], ah1, bC + 2); mma8(acc[1][3], al1, bC + 2);       \
        }                                                                     \
    } while (0)

    // --- phase 1: K 0..63 ---
    BUILD_HALF(0);
    asm volatile("cp.async.wait_group 0;" ::: "memory");
    __syncthreads();
    MMA_HALF(bB0);
    __syncthreads();          // A half-plane reuse guard

    // --- phase 2: K 64..127 ---
    BUILD_HALF(64);
    __syncthreads();
    MMA_HALF(bB0 + (OFF_B1 - OFF_B0));

    // --- epilogue: store h_l, per-channel stats (shfl-reduced over lg) ---
#pragma unroll
    for (int mt = 0; mt < 2; mt++) {
        long rA = p0 + wm * 32 + mt * 16 + lg;
        long rB = rA + 8;
        bool vA = (rA < MKP), vB = (rB < MKP);
#pragma unroll
        for (int nt = 0; nt < 4; nt++) {
            int c0 = wn * 32 + nt * 8 + lq * 2;
            if (vA) *(float2*)&g_h[rA * 128 + c0] = make_float2(acc[mt][nt][0], acc[mt][nt][1]);
            if (vB) *(float2*)&g_h[rB * 128 + c0] = make_float2(acc[mt][nt][2], acc[mt][nt][3]);
        }
    }
#pragma unroll
    for (int nt = 0; nt < 4; nt++) {
        int c0 = wn * 32 + nt * 8 + lq * 2;
#pragma unroll
        for (int par = 0; par < 2; par++) {
            float v0 = acc[0][nt][par],     v1 = acc[0][nt][2 + par];
            float v2 = acc[1][nt][par],     v3 = acc[1][nt][2 + par];
            float s = (v0 + v1) + (v2 + v3);
            float q = fmaf(v0, v0, fmaf(v1, v1, fmaf(v2, v2, v3 * v3)));
            s += __shfl_xor_sync(0xffffffffu, s, 4);
            q += __shfl_xor_sync(0xffffffffu, q, 4);
            s += __shfl_xor_sync(0xffffffffu, s, 8);
            q += __shfl_xor_sync(0xffffffffu, q, 8);
            s += __shfl_xor_sync(0xffffffffu, s, 16);
            q += __shfl_xor_sync(0xffffffffu, q, 16);
            if (lg == 0) {
                atomicAdd(&red[c0 + par], s);
                atomicAdd(&red[128 + c0 + par], q);
            }
        }
    }
    __syncthreads();
    if (tid < 128) {
        atomicAdd(&g_sum[statL * 128 + tid], (double)red[tid]);
        atomicAdd(&g_ssq[statL * 128 + tid], (double)red[128 + tid]);
    }
}

// ---------------- final: act7 -> logits -> softmax(K) -> gather+weighted sum ----------------
__global__ void k_final(const float* __restrict__ xfeat, const int* __restrict__ idx,
                        const float* __restrict__ fw, const float* __restrict__ fb,
                        float* __restrict__ out) {
    __shared__ float prod[20][128];
    __shared__ float wsm[20];
    __shared__ float logit[20];
    __shared__ int   idxs[20];

    const int m = blockIdx.x;
    const int tid = threadIdx.x;  // 128
    const float sc = g_scale[7 * 128 + tid];
    const float sh = g_shift[7 * 128 + tid];
    const float f  = fw[tid];
    const float* hrow = g_h + (long)m * 20 * 128;

    if (tid < 20) idxs[tid] = idx[m * 20 + tid];
#pragma unroll
    for (int k = 0; k < 20; k++) {
        float v = hrow[k * 128 + tid];
        prod[k][tid] = __sinf(fmaf(sc, v, sh)) * f;
    }
    __syncthreads();

    const int w = tid >> 5, lane = tid & 31;
    for (int k = w; k < 20; k += 4) {
        float sum = prod[k][lane] + prod[k][lane + 32] + prod[k][lane + 64] + prod[k][lane + 96];
        for (int off = 16; off; off >>= 1) sum += __shfl_down_sync(0xffffffffu, sum, off);
        if (lane == 0) logit[k] = sum + fb[0];
    }
    __syncthreads();

    if (tid < 32) {
        float l = (tid < 20) ? logit[tid] : -INFINITY;
        float mx = l;
        for (int off = 16; off; off >>= 1) mx = fmaxf(mx, __shfl_xor_sync(0xffffffffu, mx, off));
        float e = (tid < 20) ? expf(l - mx) : 0.f;
        float ss = e;
        for (int off = 16; off; off >>= 1) ss += __shfl_xor_sync(0xffffffffu, ss, off);
        if (tid < 20) wsm[tid] = e / ss;
    }
    __syncthreads();

    float acc = 0.f;
#pragma unroll
    for (int k = 0; k < 20; k++)
        acc += wsm[k] * xfeat[(long)idxs[k] * 128 + tid];
    out[(long)m * 128 + tid] = acc;
}

// ---------------- launch ----------------
extern "C" void kernel_launch(void* const* d_in, const int* in_sizes, int n_in,
                              void* d_out, int out_size) {
    const float* xfeat  = (const float*)d_in[0];  // (1, N, 128)
    const float* w_up   = (const float*)d_in[1];  // (1, 7, M, K)
    const int*   idx    = (const int*)d_in[2];    // (1, M, K)
    const float* conv0  = (const float*)d_in[3];  // (128, 7)
    const float* convs  = (const float*)d_in[4];  // (7, 128, 128)
    const float* gammas = (const float*)d_in[5];  // (8, 128)
    const float* betas  = (const float*)d_in[6];  // (8, 128)
    const float* fw     = (const float*)d_in[7];  // (1, 128)
    const float* fb     = (const float*)d_in[8];  // (1,)
    float* out = (float*)d_out;

    cudaFuncSetAttribute(k_gemm, cudaFuncAttributeMaxDynamicSharedMemorySize, SMEM_TOTAL);

    k_zero<<<1, 256>>>();
    k_prep<<<(7 * 2 * 128 * PKA + 255) / 256, 256>>>(convs);
    k_instats<<<256, 256>>>(w_up);
    k_fin0<<<1, 128>>>(conv0, gammas, betas);

    // Layer 1: act0 from raw input (conv0 scalar + BN0 + sin), GEMM W1, stats
    k_gemm<<<NBLK2, 256, SMEM_TOTAL>>>(w_up, conv0, 0, 0, 1, 0);
    k_fin<<<1, 128>>>(1, gammas, betas);

    // Layers 2..7
    for (int i = 2; i <= 7; i++) {
        k_gemm<<<NBLK2, 256, SMEM_TOTAL>>>(nullptr, nullptr, i - 1, i - 1, i, 1);
        k_fin<<<1, 128>>>(i, gammas, betas);
    }

    k_final<<<MM, 128>>>(xfeat, idx, fw, fb, out);
}